// round 5
// baseline (speedup 1.0000x reference)
#include <cuda_runtime.h>

// Problem constants (B=8, C=64, H=W=256, GROUPS=32, PATCH=8)
#define HW      65536
#define CHN     64
#define BATCH   8
#define NPIX    128           // pixels per conv block
#define EPSV    1e-5f

// ---------------- scratch (device globals; no allocation allowed) ----------
__device__ float g_qk[2u * BATCH * CHN * HW];     // [t][b][c][hw]  (q then k), 268MB
__device__ float g_psum[2 * BATCH * 32 * 512];    // per-block partial sums
__device__ float g_pss [2 * BATCH * 32 * 512];    // per-block partial sum-of-squares
__device__ float g_scale[2 * BATCH * CHN];        // GN folded: per (t,b,c) scale
__device__ float g_bias [2 * BATCH * CHN];        // GN folded: per (t,b,c) bias
__device__ float g_Wt[2 * CHN * CHN];             // W transposed: [t][c][o]

// ---------------- K0: transpose weights into scratch ------------------------
__global__ void k_wt(const float* __restrict__ Wq, const float* __restrict__ Wk)
{
    const float* Wm = blockIdx.x ? Wk : Wq;
    float* o = g_Wt + blockIdx.x * CHN * CHN;
    const int tid = threadIdx.x;
#pragma unroll
    for (int i = 0; i < 16; ++i) {
        int e = i * 256 + tid;
        int r = e >> 6, c = e & 63;       // r = out-channel, c = in-channel
        o[c * CHN + r] = Wm[e];           // Wt[c][o] = W[o][c]
    }
}

// ---------------- K1: 1x1 conv (GEMM) + deterministic group-stat partials ---
__global__ __launch_bounds__(256) void k_conv(const float* __restrict__ x, int t)
{
    __shared__ float Xs[64][128];   // [c][pixel]  32KB
    __shared__ float Ws[64][64];    // [c][o]      16KB  (total 48KB exactly)

    const int b   = blockIdx.y;
    const int tid = threadIdx.x;
    const int p0  = blockIdx.x * NPIX;

    // load transposed W (linear, coalesced, conflict-free)
    {
        const float4* wt4 = reinterpret_cast<const float4*>(g_Wt + t * CHN * CHN);
        float4* ws4 = reinterpret_cast<float4*>(&Ws[0][0]);
#pragma unroll
        for (int i = 0; i < 4; ++i) ws4[i * 256 + tid] = wt4[i * 256 + tid];
    }
    // load X tile [64 c][128 pix] via float4
    {
        const float4* xb4 = reinterpret_cast<const float4*>(x + (size_t)b * CHN * HW + p0);
#pragma unroll
        for (int i = 0; i < 8; ++i) {
            int e = i * 256 + tid;
            int c = e >> 5, q = e & 31;
            *reinterpret_cast<float4*>(&Xs[c][q * 4]) = xb4[(size_t)c * (HW / 4) + q];
        }
    }
    __syncthreads();

    const int tx = tid & 31;       // pixel tile: tx*4 .. tx*4+3
    const int ty = tid >> 5;       // out-channel tile: ty*8 .. ty*8+7
    float acc[8][4];
#pragma unroll
    for (int a = 0; a < 8; ++a)
#pragma unroll
        for (int p = 0; p < 4; ++p) acc[a][p] = 0.f;

#pragma unroll 8
    for (int k = 0; k < 64; ++k) {
        float4 xv = *reinterpret_cast<const float4*>(&Xs[k][tx * 4]);
        float4 w0 = *reinterpret_cast<const float4*>(&Ws[k][ty * 8]);
        float4 w1 = *reinterpret_cast<const float4*>(&Ws[k][ty * 8 + 4]);
        float xs[4] = {xv.x, xv.y, xv.z, xv.w};
        float wv[8] = {w0.x, w0.y, w0.z, w0.w, w1.x, w1.y, w1.z, w1.w};
#pragma unroll
        for (int a = 0; a < 8; ++a)
#pragma unroll
            for (int p = 0; p < 4; ++p)
                acc[a][p] = fmaf(wv[a], xs[p], acc[a][p]);
    }

    // write q/k (STG.128, fully coalesced)
    {
        float* ob = g_qk + (size_t)t * BATCH * CHN * HW + (size_t)b * CHN * HW + p0;
#pragma unroll
        for (int a = 0; a < 8; ++a) {
            int o = ty * 8 + a;
            *reinterpret_cast<float4*>(&ob[(size_t)o * HW + tx * 4]) =
                make_float4(acc[a][0], acc[a][1], acc[a][2], acc[a][3]);
        }
    }

    // group stats: channels (2g,2g+1); this warp covers all 128 pixels for its 8 channels
#pragma unroll
    for (int gl = 0; gl < 4; ++gl) {
        float s = 0.f, ss = 0.f;
#pragma unroll
        for (int a = gl * 2; a < gl * 2 + 2; ++a)
#pragma unroll
            for (int p = 0; p < 4; ++p) { float v = acc[a][p]; s += v; ss += v * v; }
#pragma unroll
        for (int m = 16; m > 0; m >>= 1) {
            s  += __shfl_xor_sync(0xffffffffu, s,  m);
            ss += __shfl_xor_sync(0xffffffffu, ss, m);
        }
        if (tx == 0) {
            int g   = ty * 4 + gl;
            int idx = ((t * BATCH + b) * 32 + g) * 512 + blockIdx.x;
            g_psum[idx] = s;
            g_pss[idx]  = ss;
        }
    }
}

// ---------------- K2: finalize stats -> per-channel scale/bias --------------
__global__ void k_stats(const float* __restrict__ gq, const float* __restrict__ bq,
                        const float* __restrict__ gk, const float* __restrict__ bk)
{
    const int id  = blockIdx.x;   // t*256 + b*32 + g
    const int tid = threadIdx.x;
    const float* ps = g_psum + (size_t)id * 512;
    const float* pq = g_pss  + (size_t)id * 512;
    float s  = ps[tid] + ps[tid + 256];
    float ss = pq[tid] + pq[tid + 256];
#pragma unroll
    for (int m = 16; m > 0; m >>= 1) {
        s  += __shfl_xor_sync(0xffffffffu, s,  m);
        ss += __shfl_xor_sync(0xffffffffu, ss, m);
    }
    __shared__ float sh[16];
    int w = tid >> 5;
    if ((tid & 31) == 0) { sh[w] = s; sh[8 + w] = ss; }
    __syncthreads();
    if (tid == 0) {
        float S = 0.f, SS = 0.f;
#pragma unroll
        for (int i = 0; i < 8; ++i) { S += sh[i]; SS += sh[8 + i]; }
        const float inv  = 1.0f / 131072.0f;    // (C/G)*H*W = 2*65536
        float mean = S * inv;
        float var  = SS * inv - mean * mean;
        float rstd = rsqrtf(var + EPSV);
        int t = id >> 8, b = (id >> 5) & 7, g = id & 31;
        const float* ga = t ? gk : gq;
        const float* be = t ? bk : bq;
#pragma unroll
        for (int j = 0; j < 2; ++j) {
            int c = g * 2 + j;
            float sc = rstd * ga[c];
            g_scale[(t * BATCH + b) * CHN + c] = sc;
            g_bias [(t * BATCH + b) * CHN + c] = be[c] - mean * sc;
        }
    }
}

// ---------------- K3: windowed cross-attention + residual -------------------
__global__ __launch_bounds__(256) void k_attn(const float* __restrict__ xlow,
                                              float* __restrict__ outp)
{
    __shared__ float bufA[64][68];   // q_sT[c][px] -> P natural -> P_T -> out_s
    __shared__ float bufK[64][68];   // k_sT[c][px] -> K_T[kp][c]

    const int b  = blockIdx.y;
    const int wi = blockIdx.x;
    const int h0 = (wi >> 5) * 8, w0 = (wi & 31) * 8;
    const int tid = threadIdx.x;
    const size_t gb = (size_t)b * CHN * HW;
    const float* qg = g_qk + gb;
    const float* kg = g_qk + (size_t)BATCH * CHN * HW + gb;

    // load with folded GroupNorm, channel-major [c][px]
#pragma unroll
    for (int i = 0; i < 16; ++i) {
        int e = i * 256 + tid;
        int c = e >> 6, px = e & 63;
        size_t ga = (size_t)c * HW + (size_t)(h0 + (px >> 3)) * 256 + (w0 + (px & 7));
        bufA[c][px] = qg[ga] * g_scale[b * CHN + c]            + g_bias[b * CHN + c];
        bufK[c][px] = kg[ga] * g_scale[(BATCH + b) * CHN + c]  + g_bias[(BATCH + b) * CHN + c];
    }
    __syncthreads();

    const int tx = tid & 15;   // key-pixel / channel tile
    const int ty = tid >> 4;   // query-pixel tile
    float s[4][4];
#pragma unroll
    for (int i = 0; i < 4; ++i)
#pragma unroll
        for (int j = 0; j < 4; ++j) s[i][j] = 0.f;

    // GEMM1: S[q][k] = sum_c q[c][q] * k[c][k]
#pragma unroll 8
    for (int k = 0; k < 64; ++k) {
        float4 qv = *reinterpret_cast<const float4*>(&bufA[k][ty * 4]);
        float4 kv = *reinterpret_cast<const float4*>(&bufK[k][tx * 4]);
        float qa[4] = {qv.x, qv.y, qv.z, qv.w};
        float ka[4] = {kv.x, kv.y, kv.z, kv.w};
#pragma unroll
        for (int i = 0; i < 4; ++i)
#pragma unroll
            for (int j = 0; j < 4; ++j)
                s[i][j] = fmaf(qa[i], ka[j], s[i][j]);
    }

    // softmax over key dim (tx group of 16 lanes), scale 1/sqrt(64)
#pragma unroll
    for (int i = 0; i < 4; ++i) {
#pragma unroll
        for (int j = 0; j < 4; ++j) s[i][j] *= 0.125f;
        float m = fmaxf(fmaxf(s[i][0], s[i][1]), fmaxf(s[i][2], s[i][3]));
#pragma unroll
        for (int msk = 8; msk > 0; msk >>= 1)
            m = fmaxf(m, __shfl_xor_sync(0xffffffffu, m, msk));
        float r = 0.f;
#pragma unroll
        for (int j = 0; j < 4; ++j) { s[i][j] = __expf(s[i][j] - m); r += s[i][j]; }
#pragma unroll
        for (int msk = 8; msk > 0; msk >>= 1)
            r += __shfl_xor_sync(0xffffffffu, r, msk);
        float inv = __fdividef(1.0f, r);
#pragma unroll
        for (int j = 0; j < 4; ++j) s[i][j] *= inv;
    }
    __syncthreads();   // all GEMM1 reads of bufA/bufK finished

    // store P natural [q][kp] into bufA; stage K for in-place transpose
    float kt[16];
#pragma unroll
    for (int i = 0; i < 4; ++i)
#pragma unroll
        for (int j = 0; j < 4; ++j)
            bufA[ty * 4 + i][tx * 4 + j] = s[i][j];
#pragma unroll
    for (int i = 0; i < 16; ++i) {
        int e = i * 256 + tid;
        kt[i] = bufK[e >> 6][e & 63];
    }
    __syncthreads();   // P fully written, K fully staged

    // write K transposed [kp][c]; stage P for transpose
    float pt[16];
#pragma unroll
    for (int i = 0; i < 16; ++i) {
        int e = i * 256 + tid;
        bufK[e & 63][e >> 6] = kt[i];
        pt[i] = bufA[e >> 6][e & 63];
    }
    __syncthreads();   // K_T written, P fully staged

    // write P transposed [kp][q]
#pragma unroll
    for (int i = 0; i < 16; ++i) {
        int e = i * 256 + tid;
        bufA[e & 63][e >> 6] = pt[i];
    }
    __syncthreads();

    // GEMM2: out[q][c] = sum_kp P_T[kp][q] * K_T[kp][c]
    float o[4][4];
#pragma unroll
    for (int i = 0; i < 4; ++i)
#pragma unroll
        for (int j = 0; j < 4; ++j) o[i][j] = 0.f;
#pragma unroll 8
    for (int k = 0; k < 64; ++k) {
        float4 pv = *reinterpret_cast<const float4*>(&bufA[k][ty * 4]);
        float4 kv = *reinterpret_cast<const float4*>(&bufK[k][tx * 4]);
        float pa[4] = {pv.x, pv.y, pv.z, pv.w};
        float ka[4] = {kv.x, kv.y, kv.z, kv.w};
#pragma unroll
        for (int i = 0; i < 4; ++i)
#pragma unroll
            for (int j = 0; j < 4; ++j)
                o[i][j] = fmaf(pa[i], ka[j], o[i][j]);
    }
    __syncthreads();   // GEMM2 reads done

    // stage output [px][c] in shared for coalesced global writes
#pragma unroll
    for (int i = 0; i < 4; ++i)
#pragma unroll
        for (int j = 0; j < 4; ++j)
            bufA[ty * 4 + i][tx * 4 + j] = o[i][j];
    __syncthreads();

    const float* xb = xlow + gb;
    float* ob = outp + gb;
#pragma unroll
    for (int i = 0; i < 16; ++i) {
        int e = i * 256 + tid;
        int c = e >> 6, px = e & 63;
        size_t ga = (size_t)c * HW + (size_t)(h0 + (px >> 3)) * 256 + (w0 + (px & 7));
        ob[ga] = bufA[px][c] + xb[ga];
    }
}

// ---------------- launch -----------------------------------------------------
extern "C" void kernel_launch(void* const* d_in, const int* in_sizes, int n_in,
                              void* d_out, int out_size)
{
    (void)in_sizes; (void)n_in; (void)out_size;
    const float* x_low  = (const float*)d_in[0];
    const float* x_high = (const float*)d_in[1];
    const float* Wq = (const float*)d_in[2];
    const float* Wk = (const float*)d_in[3];
    const float* gq = (const float*)d_in[4];
    const float* bq = (const float*)d_in[5];
    const float* gk = (const float*)d_in[6];
    const float* bk = (const float*)d_in[7];
    float* out = (float*)d_out;

    k_wt  <<<2, 256>>>(Wq, Wk);
    k_conv<<<dim3(512, BATCH), 256>>>(x_low,  0);
    k_conv<<<dim3(512, BATCH), 256>>>(x_high, 1);
    k_stats<<<512, 256>>>(gq, bq, gk, bk);
    k_attn<<<dim3(1024, BATCH), 256>>>(x_low, out);
}

// round 6
// speedup vs baseline: 1.0001x; 1.0001x over previous
#include <cuda_runtime.h>

// Problem constants (B=8, C=64, H=W=256, GROUPS=32, PATCH=8)
#define HW      65536
#define CHN     64
#define BATCH   8
#define NPIX    128           // pixels per conv block
#define EPSV    1e-5f

// ---------------- scratch (device globals; no allocation allowed) ----------
__device__ float g_qk[2u * BATCH * CHN * HW];     // [t][b][c][hw]  (q then k), 268MB
__device__ float g_psum[2 * BATCH * 32 * 512];    // per-block partial sums
__device__ float g_pss [2 * BATCH * 32 * 512];    // per-block partial sum-of-squares
__device__ float g_scale[2 * BATCH * CHN];        // GN folded: per (t,b,c) scale
__device__ float g_bias [2 * BATCH * CHN];        // GN folded: per (t,b,c) bias
__device__ float g_Wt[2 * CHN * CHN];             // W transposed: [t][c][o]

// ---------------- K0: transpose weights into scratch ------------------------
__global__ void k_wt(const float* __restrict__ Wq, const float* __restrict__ Wk)
{
    const float* Wm = blockIdx.x ? Wk : Wq;
    float* o = g_Wt + blockIdx.x * CHN * CHN;
    const int tid = threadIdx.x;
#pragma unroll
    for (int i = 0; i < 16; ++i) {
        int e = i * 256 + tid;
        int r = e >> 6, c = e & 63;       // r = out-channel, c = in-channel
        o[c * CHN + r] = Wm[e];           // Wt[c][o] = W[o][c]
    }
}

// ---------------- K1: 1x1 conv (GEMM) + deterministic group-stat partials ---
__global__ __launch_bounds__(256) void k_conv(const float* __restrict__ x, int t)
{
    __shared__ float Xs[64][128];   // [c][pixel]  32KB
    __shared__ float Ws[64][64];    // [c][o]      16KB  (total 48KB exactly)

    const int b   = blockIdx.y;
    const int tid = threadIdx.x;
    const int p0  = blockIdx.x * NPIX;

    // load transposed W (linear, coalesced, conflict-free)
    {
        const float4* wt4 = reinterpret_cast<const float4*>(g_Wt + t * CHN * CHN);
        float4* ws4 = reinterpret_cast<float4*>(&Ws[0][0]);
#pragma unroll
        for (int i = 0; i < 4; ++i) ws4[i * 256 + tid] = wt4[i * 256 + tid];
    }
    // load X tile [64 c][128 pix] via float4
    {
        const float4* xb4 = reinterpret_cast<const float4*>(x + (size_t)b * CHN * HW + p0);
#pragma unroll
        for (int i = 0; i < 8; ++i) {
            int e = i * 256 + tid;
            int c = e >> 5, q = e & 31;
            *reinterpret_cast<float4*>(&Xs[c][q * 4]) = xb4[(size_t)c * (HW / 4) + q];
        }
    }
    __syncthreads();

    const int tx = tid & 31;       // pixel tile: tx*4 .. tx*4+3
    const int ty = tid >> 5;       // out-channel tile: ty*8 .. ty*8+7
    float acc[8][4];
#pragma unroll
    for (int a = 0; a < 8; ++a)
#pragma unroll
        for (int p = 0; p < 4; ++p) acc[a][p] = 0.f;

#pragma unroll 8
    for (int k = 0; k < 64; ++k) {
        float4 xv = *reinterpret_cast<const float4*>(&Xs[k][tx * 4]);
        float4 w0 = *reinterpret_cast<const float4*>(&Ws[k][ty * 8]);
        float4 w1 = *reinterpret_cast<const float4*>(&Ws[k][ty * 8 + 4]);
        float xs[4] = {xv.x, xv.y, xv.z, xv.w};
        float wv[8] = {w0.x, w0.y, w0.z, w0.w, w1.x, w1.y, w1.z, w1.w};
#pragma unroll
        for (int a = 0; a < 8; ++a)
#pragma unroll
            for (int p = 0; p < 4; ++p)
                acc[a][p] = fmaf(wv[a], xs[p], acc[a][p]);
    }

    // write q/k (STG.128, fully coalesced)
    {
        float* ob = g_qk + (size_t)t * BATCH * CHN * HW + (size_t)b * CHN * HW + p0;
#pragma unroll
        for (int a = 0; a < 8; ++a) {
            int o = ty * 8 + a;
            *reinterpret_cast<float4*>(&ob[(size_t)o * HW + tx * 4]) =
                make_float4(acc[a][0], acc[a][1], acc[a][2], acc[a][3]);
        }
    }

    // group stats: channels (2g,2g+1); this warp covers all 128 pixels for its 8 channels
#pragma unroll
    for (int gl = 0; gl < 4; ++gl) {
        float s = 0.f, ss = 0.f;
#pragma unroll
        for (int a = gl * 2; a < gl * 2 + 2; ++a)
#pragma unroll
            for (int p = 0; p < 4; ++p) { float v = acc[a][p]; s += v; ss += v * v; }
#pragma unroll
        for (int m = 16; m > 0; m >>= 1) {
            s  += __shfl_xor_sync(0xffffffffu, s,  m);
            ss += __shfl_xor_sync(0xffffffffu, ss, m);
        }
        if (tx == 0) {
            int g   = ty * 4 + gl;
            int idx = ((t * BATCH + b) * 32 + g) * 512 + blockIdx.x;
            g_psum[idx] = s;
            g_pss[idx]  = ss;
        }
    }
}

// ---------------- K2: finalize stats -> per-channel scale/bias --------------
__global__ void k_stats(const float* __restrict__ gq, const float* __restrict__ bq,
                        const float* __restrict__ gk, const float* __restrict__ bk)
{
    const int id  = blockIdx.x;   // t*256 + b*32 + g
    const int tid = threadIdx.x;
    const float* ps = g_psum + (size_t)id * 512;
    const float* pq = g_pss  + (size_t)id * 512;
    float s  = ps[tid] + ps[tid + 256];
    float ss = pq[tid] + pq[tid + 256];
#pragma unroll
    for (int m = 16; m > 0; m >>= 1) {
        s  += __shfl_xor_sync(0xffffffffu, s,  m);
        ss += __shfl_xor_sync(0xffffffffu, ss, m);
    }
    __shared__ float sh[16];
    int w = tid >> 5;
    if ((tid & 31) == 0) { sh[w] = s; sh[8 + w] = ss; }
    __syncthreads();
    if (tid == 0) {
        float S = 0.f, SS = 0.f;
#pragma unroll
        for (int i = 0; i < 8; ++i) { S += sh[i]; SS += sh[8 + i]; }
        const float inv  = 1.0f / 131072.0f;    // (C/G)*H*W = 2*65536
        float mean = S * inv;
        float var  = SS * inv - mean * mean;
        float rstd = rsqrtf(var + EPSV);
        int t = id >> 8, b = (id >> 5) & 7, g = id & 31;
        const float* ga = t ? gk : gq;
        const float* be = t ? bk : bq;
#pragma unroll
        for (int j = 0; j < 2; ++j) {
            int c = g * 2 + j;
            float sc = rstd * ga[c];
            g_scale[(t * BATCH + b) * CHN + c] = sc;
            g_bias [(t * BATCH + b) * CHN + c] = be[c] - mean * sc;
        }
    }
}

// ---------------- K3: windowed cross-attention + residual -------------------
__global__ __launch_bounds__(256) void k_attn(const float* __restrict__ xlow,
                                              float* __restrict__ outp)
{
    __shared__ float bufA[64][68];   // q_sT[c][px] -> P natural -> P_T -> out_s
    __shared__ float bufK[64][68];   // k_sT[c][px] -> K_T[kp][c]

    const int b  = blockIdx.y;
    const int wi = blockIdx.x;
    const int h0 = (wi >> 5) * 8, w0 = (wi & 31) * 8;
    const int tid = threadIdx.x;
    const size_t gb = (size_t)b * CHN * HW;
    const float* qg = g_qk + gb;
    const float* kg = g_qk + (size_t)BATCH * CHN * HW + gb;

    // load with folded GroupNorm, channel-major [c][px]
#pragma unroll
    for (int i = 0; i < 16; ++i) {
        int e = i * 256 + tid;
        int c = e >> 6, px = e & 63;
        size_t ga = (size_t)c * HW + (size_t)(h0 + (px >> 3)) * 256 + (w0 + (px & 7));
        bufA[c][px] = qg[ga] * g_scale[b * CHN + c]            + g_bias[b * CHN + c];
        bufK[c][px] = kg[ga] * g_scale[(BATCH + b) * CHN + c]  + g_bias[(BATCH + b) * CHN + c];
    }
    __syncthreads();

    const int tx = tid & 15;   // key-pixel / channel tile
    const int ty = tid >> 4;   // query-pixel tile
    float s[4][4];
#pragma unroll
    for (int i = 0; i < 4; ++i)
#pragma unroll
        for (int j = 0; j < 4; ++j) s[i][j] = 0.f;

    // GEMM1: S[q][k] = sum_c q[c][q] * k[c][k]
#pragma unroll 8
    for (int k = 0; k < 64; ++k) {
        float4 qv = *reinterpret_cast<const float4*>(&bufA[k][ty * 4]);
        float4 kv = *reinterpret_cast<const float4*>(&bufK[k][tx * 4]);
        float qa[4] = {qv.x, qv.y, qv.z, qv.w};
        float ka[4] = {kv.x, kv.y, kv.z, kv.w};
#pragma unroll
        for (int i = 0; i < 4; ++i)
#pragma unroll
            for (int j = 0; j < 4; ++j)
                s[i][j] = fmaf(qa[i], ka[j], s[i][j]);
    }

    // softmax over key dim (tx group of 16 lanes), scale 1/sqrt(64)
#pragma unroll
    for (int i = 0; i < 4; ++i) {
#pragma unroll
        for (int j = 0; j < 4; ++j) s[i][j] *= 0.125f;
        float m = fmaxf(fmaxf(s[i][0], s[i][1]), fmaxf(s[i][2], s[i][3]));
#pragma unroll
        for (int msk = 8; msk > 0; msk >>= 1)
            m = fmaxf(m, __shfl_xor_sync(0xffffffffu, m, msk));
        float r = 0.f;
#pragma unroll
        for (int j = 0; j < 4; ++j) { s[i][j] = __expf(s[i][j] - m); r += s[i][j]; }
#pragma unroll
        for (int msk = 8; msk > 0; msk >>= 1)
            r += __shfl_xor_sync(0xffffffffu, r, msk);
        float inv = __fdividef(1.0f, r);
#pragma unroll
        for (int j = 0; j < 4; ++j) s[i][j] *= inv;
    }
    __syncthreads();   // all GEMM1 reads of bufA/bufK finished

    // store P natural [q][kp] into bufA; stage K for in-place transpose
    float kt[16];
#pragma unroll
    for (int i = 0; i < 4; ++i)
#pragma unroll
        for (int j = 0; j < 4; ++j)
            bufA[ty * 4 + i][tx * 4 + j] = s[i][j];
#pragma unroll
    for (int i = 0; i < 16; ++i) {
        int e = i * 256 + tid;
        kt[i] = bufK[e >> 6][e & 63];
    }
    __syncthreads();   // P fully written, K fully staged

    // write K transposed [kp][c]; stage P for transpose
    float pt[16];
#pragma unroll
    for (int i = 0; i < 16; ++i) {
        int e = i * 256 + tid;
        bufK[e & 63][e >> 6] = kt[i];
        pt[i] = bufA[e >> 6][e & 63];
    }
    __syncthreads();   // K_T written, P fully staged

    // write P transposed [kp][q]
#pragma unroll
    for (int i = 0; i < 16; ++i) {
        int e = i * 256 + tid;
        bufA[e & 63][e >> 6] = pt[i];
    }
    __syncthreads();

    // GEMM2: out[q][c] = sum_kp P_T[kp][q] * K_T[kp][c]
    float o[4][4];
#pragma unroll
    for (int i = 0; i < 4; ++i)
#pragma unroll
        for (int j = 0; j < 4; ++j) o[i][j] = 0.f;
#pragma unroll 8
    for (int k = 0; k < 64; ++k) {
        float4 pv = *reinterpret_cast<const float4*>(&bufA[k][ty * 4]);
        float4 kv = *reinterpret_cast<const float4*>(&bufK[k][tx * 4]);
        float pa[4] = {pv.x, pv.y, pv.z, pv.w};
        float ka[4] = {kv.x, kv.y, kv.z, kv.w};
#pragma unroll
        for (int i = 0; i < 4; ++i)
#pragma unroll
            for (int j = 0; j < 4; ++j)
                o[i][j] = fmaf(pa[i], ka[j], o[i][j]);
    }
    __syncthreads();   // GEMM2 reads done

    // stage output [px][c] in shared for coalesced global writes
#pragma unroll
    for (int i = 0; i < 4; ++i)
#pragma unroll
        for (int j = 0; j < 4; ++j)
            bufA[ty * 4 + i][tx * 4 + j] = o[i][j];
    __syncthreads();

    const float* xb = xlow + gb;
    float* ob = outp + gb;
#pragma unroll
    for (int i = 0; i < 16; ++i) {
        int e = i * 256 + tid;
        int c = e >> 6, px = e & 63;
        size_t ga = (size_t)c * HW + (size_t)(h0 + (px >> 3)) * 256 + (w0 + (px & 7));
        ob[ga] = bufA[px][c] + xb[ga];
    }
}

// ---------------- launch -----------------------------------------------------
extern "C" void kernel_launch(void* const* d_in, const int* in_sizes, int n_in,
                              void* d_out, int out_size)
{
    (void)in_sizes; (void)n_in; (void)out_size;
    const float* x_low  = (const float*)d_in[0];
    const float* x_high = (const float*)d_in[1];
    const float* Wq = (const float*)d_in[2];
    const float* Wk = (const float*)d_in[3];
    const float* gq = (const float*)d_in[4];
    const float* bq = (const float*)d_in[5];
    const float* gk = (const float*)d_in[6];
    const float* bk = (const float*)d_in[7];
    float* out = (float*)d_out;

    k_wt  <<<2, 256>>>(Wq, Wk);
    k_conv<<<dim3(512, BATCH), 256>>>(x_low,  0);
    k_conv<<<dim3(512, BATCH), 256>>>(x_high, 1);
    k_stats<<<512, 256>>>(gq, bq, gk, bk);
    k_attn<<<dim3(1024, BATCH), 256>>>(x_low, out);
}

// round 7
// speedup vs baseline: 1.0499x; 1.0499x over previous
#include <cuda_runtime.h>

// Problem constants (B=8, C=64, H=W=256, GROUPS=32, PATCH=8)
#define HW      65536
#define CHN     64
#define BATCH   8
#define NPIX    128           // pixels per conv block
#define EPSV    1e-5f

typedef unsigned long long u64;

// ---- packed f32x2 helpers (sm_103a; ptxas never auto-fuses these) ----------
__device__ __forceinline__ u64 pack2(float lo, float hi) {
    u64 r;
    asm("mov.b64 %0, {%1, %2};" : "=l"(r) : "f"(lo), "f"(hi));
    return r;
}
__device__ __forceinline__ void unpack2(u64 v, float& lo, float& hi) {
    asm("mov.b64 {%0, %1}, %2;" : "=f"(lo), "=f"(hi) : "l"(v));
}
__device__ __forceinline__ void fma2(u64& d, u64 a, u64 b) {
    asm("fma.rn.f32x2 %0, %1, %2, %0;" : "+l"(d) : "l"(a), "l"(b));
}

// ---------------- scratch (device globals; no allocation allowed) ----------
__device__ float g_qk[2u * BATCH * CHN * HW];     // [t][b][c][hw]  (q then k)
__device__ float g_psum[2 * BATCH * 32 * 512];    // per-block partial sums
__device__ float g_pss [2 * BATCH * 32 * 512];    // per-block partial sum-of-squares
__device__ float g_scale[2 * BATCH * CHN];        // GN folded: per (t,b,c) scale
__device__ float g_bias [2 * BATCH * CHN];        // GN folded: per (t,b,c) bias
__device__ float g_Wt[2 * CHN * CHN];             // W transposed: [t][c][o]

// ---------------- K0: transpose weights into scratch ------------------------
__global__ void k_wt(const float* __restrict__ Wq, const float* __restrict__ Wk)
{
    const float* Wm = blockIdx.x ? Wk : Wq;
    float* o = g_Wt + blockIdx.x * CHN * CHN;
    const int tid = threadIdx.x;
#pragma unroll
    for (int i = 0; i < 16; ++i) {
        int e = i * 256 + tid;
        int r = e >> 6, c = e & 63;       // r = out-channel, c = in-channel
        o[c * CHN + r] = Wm[e];           // Wt[c][o] = W[o][c]
    }
}

// ---------------- K1: 1x1 conv (GEMM, f32x2) + group-stat partials ----------
__global__ __launch_bounds__(256) void k_conv(const float* __restrict__ xlow,
                                              const float* __restrict__ xhigh)
{
    __shared__ float Xs[64][128];   // [c][pixel]  32KB
    __shared__ float Ws[64][64];    // [c][o]      16KB

    const int t   = blockIdx.z;
    const float* x = t ? xhigh : xlow;
    const int b   = blockIdx.y;
    const int tid = threadIdx.x;
    const int p0  = blockIdx.x * NPIX;

    // load transposed W (linear, coalesced, conflict-free)
    {
        const float4* wt4 = reinterpret_cast<const float4*>(g_Wt + t * CHN * CHN);
        float4* ws4 = reinterpret_cast<float4*>(&Ws[0][0]);
#pragma unroll
        for (int i = 0; i < 4; ++i) ws4[i * 256 + tid] = wt4[i * 256 + tid];
    }
    // load X tile [64 c][128 pix] via float4
    {
        const float4* xb4 = reinterpret_cast<const float4*>(x + (size_t)b * CHN * HW + p0);
#pragma unroll
        for (int i = 0; i < 8; ++i) {
            int e = i * 256 + tid;
            int c = e >> 5, q = e & 31;
            *reinterpret_cast<float4*>(&Xs[c][q * 4]) = xb4[(size_t)c * (HW / 4) + q];
        }
    }
    __syncthreads();

    const int tx = tid & 31;       // pixel tile: tx*4 .. tx*4+3
    const int ty = tid >> 5;       // out-channel tile: ty*8 .. ty*8+7

    // acc2[ap][p]: packed pair = out-channels (2ap, 2ap+1) at pixel p
    u64 acc2[4][4];
#pragma unroll
    for (int a = 0; a < 4; ++a)
#pragma unroll
        for (int p = 0; p < 4; ++p) acc2[a][p] = 0ull;

#pragma unroll 8
    for (int k = 0; k < 64; ++k) {
        float4 xv = *reinterpret_cast<const float4*>(&Xs[k][tx * 4]);
        // natural packed channel pairs from shared (32B aligned)
        ulonglong2 w01 = *reinterpret_cast<const ulonglong2*>(&Ws[k][ty * 8]);
        ulonglong2 w23 = *reinterpret_cast<const ulonglong2*>(&Ws[k][ty * 8 + 4]);
        u64 wp[4] = {w01.x, w01.y, w23.x, w23.y};
        u64 xd[4] = {pack2(xv.x, xv.x), pack2(xv.y, xv.y),
                     pack2(xv.z, xv.z), pack2(xv.w, xv.w)};
#pragma unroll
        for (int a = 0; a < 4; ++a)
#pragma unroll
            for (int p = 0; p < 4; ++p)
                fma2(acc2[a][p], wp[a], xd[p]);
    }

    // unpack + write q/k (STG.128, fully coalesced) + group stats
    float* ob = g_qk + (size_t)t * BATCH * CHN * HW + (size_t)b * CHN * HW + p0;
#pragma unroll
    for (int ap = 0; ap < 4; ++ap) {
        float lo[4], hi[4];
#pragma unroll
        for (int p = 0; p < 4; ++p) unpack2(acc2[ap][p], lo[p], hi[p]);
        int o0 = ty * 8 + 2 * ap;
        *reinterpret_cast<float4*>(&ob[(size_t)o0 * HW + tx * 4]) =
            make_float4(lo[0], lo[1], lo[2], lo[3]);
        *reinterpret_cast<float4*>(&ob[(size_t)(o0 + 1) * HW + tx * 4]) =
            make_float4(hi[0], hi[1], hi[2], hi[3]);

        // channel pair (2ap, 2ap+1) of this ty == exactly one GN group
        float s = 0.f, ss = 0.f;
#pragma unroll
        for (int p = 0; p < 4; ++p) {
            s  += lo[p] + hi[p];
            ss += lo[p] * lo[p] + hi[p] * hi[p];
        }
#pragma unroll
        for (int m = 16; m > 0; m >>= 1) {
            s  += __shfl_xor_sync(0xffffffffu, s,  m);
            ss += __shfl_xor_sync(0xffffffffu, ss, m);
        }
        if (tx == 0) {
            int g   = ty * 4 + ap;
            int idx = ((t * BATCH + b) * 32 + g) * 512 + blockIdx.x;
            g_psum[idx] = s;
            g_pss[idx]  = ss;
        }
    }
}

// ---------------- K2: finalize stats -> per-channel scale/bias --------------
__global__ void k_stats(const float* __restrict__ gq, const float* __restrict__ bq,
                        const float* __restrict__ gk, const float* __restrict__ bk)
{
    const int id  = blockIdx.x;   // t*256 + b*32 + g
    const int tid = threadIdx.x;
    const float* ps = g_psum + (size_t)id * 512;
    const float* pq = g_pss  + (size_t)id * 512;
    float s  = ps[tid] + ps[tid + 256];
    float ss = pq[tid] + pq[tid + 256];
#pragma unroll
    for (int m = 16; m > 0; m >>= 1) {
        s  += __shfl_xor_sync(0xffffffffu, s,  m);
        ss += __shfl_xor_sync(0xffffffffu, ss, m);
    }
    __shared__ float sh[16];
    int w = tid >> 5;
    if ((tid & 31) == 0) { sh[w] = s; sh[8 + w] = ss; }
    __syncthreads();
    if (tid == 0) {
        float S = 0.f, SS = 0.f;
#pragma unroll
        for (int i = 0; i < 8; ++i) { S += sh[i]; SS += sh[8 + i]; }
        const float inv  = 1.0f / 131072.0f;    // (C/G)*H*W = 2*65536
        float mean = S * inv;
        float var  = SS * inv - mean * mean;
        float rstd = rsqrtf(var + EPSV);
        int t = id >> 8, b = (id >> 5) & 7, g = id & 31;
        const float* ga = t ? gk : gq;
        const float* be = t ? bk : bq;
#pragma unroll
        for (int j = 0; j < 2; ++j) {
            int c = g * 2 + j;
            float sc = rstd * ga[c];
            g_scale[(t * BATCH + b) * CHN + c] = sc;
            g_bias [(t * BATCH + b) * CHN + c] = be[c] - mean * sc;
        }
    }
}

// ---------------- K3: windowed cross-attention + residual (f32x2) -----------
__global__ __launch_bounds__(256) void k_attn(const float* __restrict__ xlow,
                                              float* __restrict__ outp)
{
    __shared__ float bufA[64][68];   // q_sT[c][px] -> P natural -> P_T -> out_s
    __shared__ float bufK[64][68];   // k_sT[c][px] -> K_T[kp][c]

    const int b  = blockIdx.y;
    const int wi = blockIdx.x;
    const int h0 = (wi >> 5) * 8, w0 = (wi & 31) * 8;
    const int tid = threadIdx.x;
    const size_t gb = (size_t)b * CHN * HW;
    const float* qg = g_qk + gb;
    const float* kg = g_qk + (size_t)BATCH * CHN * HW + gb;

    // load with folded GroupNorm, channel-major [c][px]
#pragma unroll
    for (int i = 0; i < 16; ++i) {
        int e = i * 256 + tid;
        int c = e >> 6, px = e & 63;
        size_t ga = (size_t)c * HW + (size_t)(h0 + (px >> 3)) * 256 + (w0 + (px & 7));
        bufA[c][px] = qg[ga] * g_scale[b * CHN + c]            + g_bias[b * CHN + c];
        bufK[c][px] = kg[ga] * g_scale[(BATCH + b) * CHN + c]  + g_bias[(BATCH + b) * CHN + c];
    }
    __syncthreads();

    const int tx = tid & 15;   // key-pixel / channel tile
    const int ty = tid >> 4;   // query-pixel tile

    // GEMM1: S[q][k] = sum_c q[c][q] * k[c][k]   (key dim packed in pairs)
    u64 s2[4][2];
#pragma unroll
    for (int i = 0; i < 4; ++i) { s2[i][0] = 0ull; s2[i][1] = 0ull; }

#pragma unroll 8
    for (int k = 0; k < 64; ++k) {
        float4 qv = *reinterpret_cast<const float4*>(&bufA[k][ty * 4]);
        ulonglong2 kv = *reinterpret_cast<const ulonglong2*>(&bufK[k][tx * 4]);
        u64 qd[4] = {pack2(qv.x, qv.x), pack2(qv.y, qv.y),
                     pack2(qv.z, qv.z), pack2(qv.w, qv.w)};
#pragma unroll
        for (int i = 0; i < 4; ++i) {
            fma2(s2[i][0], qd[i], kv.x);
            fma2(s2[i][1], qd[i], kv.y);
        }
    }

    // unpack + softmax over key dim (tx group of 16 lanes), scale 1/sqrt(64)
    float s[4][4];
#pragma unroll
    for (int i = 0; i < 4; ++i) {
        unpack2(s2[i][0], s[i][0], s[i][1]);
        unpack2(s2[i][1], s[i][2], s[i][3]);
    }
#pragma unroll
    for (int i = 0; i < 4; ++i) {
#pragma unroll
        for (int j = 0; j < 4; ++j) s[i][j] *= 0.125f;
        float m = fmaxf(fmaxf(s[i][0], s[i][1]), fmaxf(s[i][2], s[i][3]));
#pragma unroll
        for (int msk = 8; msk > 0; msk >>= 1)
            m = fmaxf(m, __shfl_xor_sync(0xffffffffu, m, msk));
        float r = 0.f;
#pragma unroll
        for (int j = 0; j < 4; ++j) { s[i][j] = __expf(s[i][j] - m); r += s[i][j]; }
#pragma unroll
        for (int msk = 8; msk > 0; msk >>= 1)
            r += __shfl_xor_sync(0xffffffffu, r, msk);
        float inv = __fdividef(1.0f, r);
#pragma unroll
        for (int j = 0; j < 4; ++j) s[i][j] *= inv;
    }
    __syncthreads();   // all GEMM1 reads of bufA/bufK finished

    // store P natural [q][kp] into bufA; stage K for in-place transpose
    float kt[16];
#pragma unroll
    for (int i = 0; i < 4; ++i)
#pragma unroll
        for (int j = 0; j < 4; ++j)
            bufA[ty * 4 + i][tx * 4 + j] = s[i][j];
#pragma unroll
    for (int i = 0; i < 16; ++i) {
        int e = i * 256 + tid;
        kt[i] = bufK[e >> 6][e & 63];
    }
    __syncthreads();   // P fully written, K fully staged

    // write K transposed [kp][c]; stage P for transpose
    float pt[16];
#pragma unroll
    for (int i = 0; i < 16; ++i) {
        int e = i * 256 + tid;
        bufK[e & 63][e >> 6] = kt[i];
        pt[i] = bufA[e >> 6][e & 63];
    }
    __syncthreads();   // K_T written, P fully staged

    // write P transposed [kp][q]
#pragma unroll
    for (int i = 0; i < 16; ++i) {
        int e = i * 256 + tid;
        bufA[e & 63][e >> 6] = pt[i];
    }
    __syncthreads();

    // GEMM2: out[q][c] = sum_kp P_T[kp][q] * K_T[kp][c]   (channel pairs packed)
    u64 o2[4][2];
#pragma unroll
    for (int i = 0; i < 4; ++i) { o2[i][0] = 0ull; o2[i][1] = 0ull; }

#pragma unroll 8
    for (int k = 0; k < 64; ++k) {
        float4 pv = *reinterpret_cast<const float4*>(&bufA[k][ty * 4]);
        ulonglong2 kv = *reinterpret_cast<const ulonglong2*>(&bufK[k][tx * 4]);
        u64 pd[4] = {pack2(pv.x, pv.x), pack2(pv.y, pv.y),
                     pack2(pv.z, pv.z), pack2(pv.w, pv.w)};
#pragma unroll
        for (int i = 0; i < 4; ++i) {
            fma2(o2[i][0], pd[i], kv.x);
            fma2(o2[i][1], pd[i], kv.y);
        }
    }
    __syncthreads();   // GEMM2 reads done

    // stage output [px][c] in shared for coalesced global writes
#pragma unroll
    for (int i = 0; i < 4; ++i) {
        float a0, a1, a2, a3;
        unpack2(o2[i][0], a0, a1);
        unpack2(o2[i][1], a2, a3);
        bufA[ty * 4 + i][tx * 4 + 0] = a0;
        bufA[ty * 4 + i][tx * 4 + 1] = a1;
        bufA[ty * 4 + i][tx * 4 + 2] = a2;
        bufA[ty * 4 + i][tx * 4 + 3] = a3;
    }
    __syncthreads();

    const float* xb = xlow + gb;
    float* ob = outp + gb;
#pragma unroll
    for (int i = 0; i < 16; ++i) {
        int e = i * 256 + tid;
        int c = e >> 6, px = e & 63;
        size_t ga = (size_t)c * HW + (size_t)(h0 + (px >> 3)) * 256 + (w0 + (px & 7));
        ob[ga] = bufA[px][c] + xb[ga];
    }
}

// ---------------- launch -----------------------------------------------------
extern "C" void kernel_launch(void* const* d_in, const int* in_sizes, int n_in,
                              void* d_out, int out_size)
{
    (void)in_sizes; (void)n_in; (void)out_size;
    const float* x_low  = (const float*)d_in[0];
    const float* x_high = (const float*)d_in[1];
    const float* Wq = (const float*)d_in[2];
    const float* Wk = (const float*)d_in[3];
    const float* gq = (const float*)d_in[4];
    const float* bq = (const float*)d_in[5];
    const float* gk = (const float*)d_in[6];
    const float* bk = (const float*)d_in[7];
    float* out = (float*)d_out;

    k_wt  <<<2, 256>>>(Wq, Wk);
    k_conv<<<dim3(512, BATCH, 2), 256>>>(x_low, x_high);
    k_stats<<<512, 256>>>(gq, bq, gk, bk);
    k_attn<<<dim3(1024, BATCH), 256>>>(x_low, out);
}